// round 16
// baseline (speedup 1.0000x reference)
#include <cuda_runtime.h>
#include <math.h>

#define N_NODES 8192
#define F_DIM   64
#define H_DIM   128
#define R_DIM   3
#define DEG     32
#define K_TOP   32
#define E_EDGES (N_NODES*DEG)
#define TEMP    0.3f
#define NEG     0.2f
#define EPS_LN  1e-5f
#define THRESH  1e-6f

#define A1_BLOCKS 256   // 32 nodes per block

typedef unsigned long long ull;

// deterministic scratch (no atomics)
__device__ float g_part_gs[A1_BLOCKS * F_DIM];
__device__ float g_part_cont[A1_BLOCKS];
__device__ float g_regime[R_DIM];
__device__ float g_amp;

// ---------------------------------------------------------------------------
// f32x2 helpers
__device__ __forceinline__ ull pk2(float x, float y) {
    ull r;
    asm("mov.b64 %0, {%1, %2};" : "=l"(r) : "f"(x), "f"(y));
    return r;
}
__device__ __forceinline__ void upk2(ull v, float& x, float& y) {
    asm("mov.b64 {%0, %1}, %2;" : "=f"(x), "=f"(y) : "l"(v));
}
__device__ __forceinline__ void fma2(ull& d, ull a, ull b) {
    asm("fma.rn.f32x2 %0, %1, %2, %0;" : "+l"(d) : "l"(a), "l"(b));
}
// 16B read-only weight load -> two packed f32x2 operands (coalesced 512B/warp)
__device__ __forceinline__ void ldg2x2(const float* p, ull& a, ull& b) {
    asm("ld.global.nc.v2.b64 {%0, %1}, [%2];" : "=l"(a), "=l"(b) : "l"(p));
}

// ---------------------------------------------------------------------------
// A1: per-block (32 nodes) partial column sums of x, and partial contagion sums
__global__ void kA1(const float* __restrict__ x,
                    const float* __restrict__ Wc1, const float* __restrict__ bc1,
                    const float* __restrict__ Wc2, const float* __restrict__ bc2) {
    __shared__ float xs[32][64];
    __shared__ float colsum[4][64];
    __shared__ float cwarp[8];
    int t = threadIdx.x, b = blockIdx.x;
    int base = b * 32;
    for (int idx = t; idx < 32 * 64; idx += 256)
        xs[idx >> 6][idx & 63] = x[base * 64 + idx];
    __syncthreads();
    {
        int col = t & 63, g = t >> 6;
        float s = 0.f;
        #pragma unroll
        for (int rr = 0; rr < 8; rr++) s += xs[g * 8 + rr][col];
        colsum[g][col] = s;
    }
    int w = t >> 5, l = t & 31;
    float a[4][4];
    #pragma unroll
    for (int q = 0; q < 4; q++) {
        a[q][0] = bc1[l]; a[q][1] = bc1[l + 32];
        a[q][2] = bc1[l + 64]; a[q][3] = bc1[l + 96];
    }
    #pragma unroll 4
    for (int d = 0; d < 64; d++) {
        const float* Wd = Wc1 + d * 128;
        float w0 = Wd[l], w1 = Wd[l + 32], w2 = Wd[l + 64], w3 = Wd[l + 96];
        #pragma unroll
        for (int q = 0; q < 4; q++) {
            float xv = xs[w * 4 + q][d];
            a[q][0] += xv * w0; a[q][1] += xv * w1;
            a[q][2] += xv * w2; a[q][3] += xv * w3;
        }
    }
    float csum = 0.f;
    #pragma unroll
    for (int q = 0; q < 4; q++) {
        float s = fmaxf(a[q][0], 0.f) * Wc2[l]      + fmaxf(a[q][1], 0.f) * Wc2[l + 32]
                + fmaxf(a[q][2], 0.f) * Wc2[l + 64] + fmaxf(a[q][3], 0.f) * Wc2[l + 96];
        #pragma unroll
        for (int off = 16; off; off >>= 1) s += __shfl_xor_sync(0xffffffffu, s, off);
        if (l == 0) csum += 1.f / (1.f + expf(-(s + bc2[0])));
    }
    if (l == 0) cwarp[w] = csum;
    __syncthreads();
    if (t < 64) g_part_gs[b * 64 + t] = colsum[0][t] + colsum[1][t] + colsum[2][t] + colsum[3][t];
    if (t == 0) {
        float s = 0.f;
        for (int i = 0; i < 8; i++) s += cwarp[i];
        g_part_cont[b] = s;
    }
}

// ---------------------------------------------------------------------------
// A2: finalize gs mean, regime probs, contagion amp
__global__ void kA2(const float* __restrict__ Wr1, const float* __restrict__ br1,
                    const float* __restrict__ Wr2, const float* __restrict__ br2) {
    __shared__ float gs[64];
    __shared__ float hr[128];
    int t = threadIdx.x;
    if (t < 64) {
        float s = 0.f;
        for (int b = 0; b < A1_BLOCKS; b++) s += g_part_gs[b * 64 + t];
        gs[t] = s / (float)N_NODES;
    }
    __syncthreads();
    {
        float a = br1[t];
        for (int d = 0; d < 64; d++) a += gs[d] * Wr1[d * 128 + t];
        hr[t] = fmaxf(a, 0.f);
    }
    __syncthreads();
    if (t == 0) {
        float lg[3];
        for (int r = 0; r < 3; r++) {
            float a = br2[r];
            for (int h = 0; h < 128; h++) a += hr[h] * Wr2[h * 3 + r];
            lg[r] = a;
        }
        float m = fmaxf(lg[0], fmaxf(lg[1], lg[2]));
        float e0 = expf(lg[0] - m), e1 = expf(lg[1] - m), e2 = expf(lg[2] - m);
        float s = e0 + e1 + e2;
        g_regime[0] = e0 / s; g_regime[1] = e1 / s; g_regime[2] = e2 / s;
        float c = 0.f;
        for (int b = 0; b < A1_BLOCKS; b++) c += g_part_cont[b];
        g_amp = 1.f + 0.5f * (c / (float)N_NODES);
    }
}

// ---------------------------------------------------------------------------
// Main per-row kernel. Shared layout (float offsets):
//   [0:64)        sx          [64:96)   tg (int)     [96:192)  sea
//   [192:448)     base_f      [448:480) raw          [480:512) sc
//   [512:608)     gpart[3][32]
//   [608:4704)    A2 : 32 rows x 32 float4 {a,a,a',a'} (16 KB)
//                 sWg0 (12 KB Wg1 stage, buffer 0) aliases it after phase 1
//   [4704:7776)   sWg1 (12 KB Wg1 stage, buffer 1)
//   [7776:15968)  P2 : 32 rows x 64 float4 {p,p,p',p'} dup (32 KB)
#define SM_A2    608
#define SM_WG1B  4704
#define SM_P2    7776
#define SM_TOTAL 15968
#define SMEM_B_BYTES (SM_TOTAL * 4)

__global__ void __launch_bounds__(256, 3) kB(
    const float* __restrict__ x, const void* __restrict__ eidx, const float* __restrict__ ea,
    const float* __restrict__ Ws1, const float* __restrict__ bs1,
    const float* __restrict__ ln_g, const float* __restrict__ ln_b,
    const float* __restrict__ Ws2, const float* __restrict__ bs2,
    const float* __restrict__ Wp,  const float* __restrict__ bp,
    const float* __restrict__ Wg1, const float* __restrict__ bg1,
    const float* __restrict__ Wg2, const float* __restrict__ bg2,
    float* __restrict__ out, int write_idx) {

    extern __shared__ float smf[];
    float* sx     = smf;
    int*   tg     = (int*)(smf + 64);
    float* sea    = smf + 96;
    float* base_f = smf + 192;
    float* raw    = smf + 448;
    float* sc     = smf + 480;
    float* gpart  = smf + 512;
    float* A2     = smf + SM_A2;     // dup-pair float4, 2 d per float4
    float* sWg0   = smf + SM_A2;     // aliases A2 after phase-1 mainloop
    float* sWg1   = smf + SM_WG1B;
    float* P2     = smf + SM_P2;     // dup-pair float4, 2 h per float4

    int t = threadIdx.x;
    int r = blockIdx.x;
    int w = t >> 5, l = t & 31;

    // ---- phase 0a: small loads -----------------------------------------
    if (t < 16) ((float4*)sx)[t] = ((const float4*)(x + r * 64))[t];
    if (t >= 64 && t < 96) {
        int j = t - 64;
        int e = r * DEG + j;
        const long long* p64 = (const long long*)eidx;
        int tgv;
        if (p64[32] == 1LL) tgv = (int)p64[E_EDGES + e];
        else                tgv = ((const int*)eidx)[E_EDGES + e];
        tg[j] = tgv;
    }
    if (t >= 96 && t < 192) sea[t - 96] = ea[r * 96 + (t - 96)];
    __syncthreads();

    // ---- phase 0b: gather A2 (all threads) + base_f (all threads) -------
    {
        const float4* x4 = (const float4*)x;
        float4* A4w = (float4*)A2;
        #pragma unroll
        for (int u = 0; u < 2; u++) {
            int idx = t + u * 256;                 // 512 float4 total
            int row = idx >> 4, d4 = idx & 15;
            float4 v = x4[tg[row] * 16 + d4];
            A4w[row * 32 + d4 * 2 + 0] = make_float4(v.x, v.x, v.y, v.y);
            A4w[row * 32 + d4 * 2 + 1] = make_float4(v.z, v.z, v.w, v.w);
        }
    }
    {
        // fused column c = t (0..127 -> Ws1, 128..255 -> Wp)
        const float* Wcol = (t < 128) ? (Ws1 + t) : (Wp + (t - 128));
        float acc0 = (t < 128) ? bs1[t] : bp[t - 128];
        #pragma unroll 8
        for (int d = 0; d < 64; d++)
            acc0 += sx[d] * Wcol[d * 128];
        base_f[t] = acc0;
    }
    __syncthreads();

    // ---- phase 1: fused [32 x 256] GEMM (H | P) -------------------------
    // warp w: matsel = w>>2 (0=H via Ws1, 1=P via Wp), rq = w&3 -> rows rq*8..rq*8+7
    // lane l: cols 4l..4l+3 of the 128-col mat (2 col-pairs)
    int matsel = w >> 2, rq = w & 3;
    int rowbase = rq * 8;
    const float* Wmat = matsel ? Wp : Ws1;
    const float* Wtgt = Wmat + 64 * 128 + 4 * l;
    ull acc[8][2];
    {
        const ull* bf = (const ull*)base_f + matsel * 64 + 2 * l;
        #pragma unroll
        for (int jj = 0; jj < 8; jj++) { acc[jj][0] = bf[0]; acc[jj][1] = bf[1]; }
    }
    {
        const ulonglong2* Arow = (const ulonglong2*)A2 + rowbase * 32;
        #pragma unroll 4
        for (int d2 = 0; d2 < 32; d2++) {
            ull w00, w01, w10, w11;
            ldg2x2(Wtgt + (2 * d2) * 128, w00, w01);        // d=2d2, cp0|cp1
            ldg2x2(Wtgt + (2 * d2 + 1) * 128, w10, w11);    // d=2d2+1
            #pragma unroll
            for (int jj = 0; jj < 8; jj++) {
                ulonglong2 av = Arow[jj * 32 + d2];
                fma2(acc[jj][0], av.x, w00); fma2(acc[jj][1], av.x, w01);
                fma2(acc[jj][0], av.y, w10); fma2(acc[jj][1], av.y, w11);
            }
        }
        // edge-attr tail (rows 128..130 of the fused weight)
        #pragma unroll
        for (int k = 0; k < 3; k++) {
            ull e0, e1;
            ldg2x2(Wmat + (128 + k) * 128 + 4 * l, e0, e1);
            #pragma unroll
            for (int jj = 0; jj < 8; jj++) {
                float sv = sea[(rowbase + jj) * 3 + k];
                ull sp = pk2(sv, sv);
                fma2(acc[jj][0], sp, e0); fma2(acc[jj][1], sp, e1);
            }
        }
    }
    __syncthreads();   // A2 reads done everywhere; sWg0 may now alias it

    // ---- stage Wg1 chunk 0 into sWg0 (LDGs in flight during epilogue) ---
    {
        const float4* srcW = (const float4*)(Wg1);
        float4* dstW = (float4*)sWg0;
        #pragma unroll
        for (int i = 0; i < 3; i++) {
            int idx = i * 256 + t;
            int rr = idx >> 8, within = idx & 255;
            dstW[rr * 256 + within] = srcW[rr * 2048 + within];
        }
    }

    // ---- phase 1 epilogue ----------------------------------------------
    if (matsel == 0) {
        // H-warps: full row in-warp -> fused LayerNorm + LeakyReLU + score
        float4 lgv = *(const float4*)(ln_g + 4 * l);
        float4 lbv = *(const float4*)(ln_b + 4 * l);
        float4 wsv = *(const float4*)(Ws2 + 4 * l);
        float bias2 = bs2[0];
        #pragma unroll
        for (int jj = 0; jj < 8; jj++) {
            float v0, v1, v2, v3;
            upk2(acc[jj][0], v0, v1); upk2(acc[jj][1], v2, v3);
            float s  = v0 + v1 + v2 + v3;
            float ss = v0 * v0 + v1 * v1 + v2 * v2 + v3 * v3;
            #pragma unroll
            for (int off = 16; off; off >>= 1) {
                s  += __shfl_xor_sync(0xffffffffu, s, off);
                ss += __shfl_xor_sync(0xffffffffu, ss, off);
            }
            float mu  = s * (1.f / 128.f);
            float var = fmaxf(ss * (1.f / 128.f) - mu * mu, 0.f);
            float inv = rsqrtf(var + EPS_LN);
            float h0 = (v0 - mu) * inv * lgv.x + lbv.x;
            float h1 = (v1 - mu) * inv * lgv.y + lbv.y;
            float h2 = (v2 - mu) * inv * lgv.z + lbv.z;
            float h3 = (v3 - mu) * inv * lgv.w + lbv.w;
            h0 = h0 >= 0.f ? h0 : NEG * h0;
            h1 = h1 >= 0.f ? h1 : NEG * h1;
            h2 = h2 >= 0.f ? h2 : NEG * h2;
            h3 = h3 >= 0.f ? h3 : NEG * h3;
            float contrib = h0 * wsv.x + h1 * wsv.y + h2 * wsv.z + h3 * wsv.w;
            #pragma unroll
            for (int off = 16; off; off >>= 1)
                contrib += __shfl_xor_sync(0xffffffffu, contrib, off);
            if (l == 0) raw[rowbase + jj] = contrib + bias2;
        }
    } else {
        // P-warps: relu + duplicated-pair stores (two float4 per row)
        float4* P4 = (float4*)P2;
        #pragma unroll
        for (int jj = 0; jj < 8; jj++) {
            float p0, p1, p2, p3;
            upk2(acc[jj][0], p0, p1); upk2(acc[jj][1], p2, p3);
            p0 = fmaxf(p0, 0.f); p1 = fmaxf(p1, 0.f);
            p2 = fmaxf(p2, 0.f); p3 = fmaxf(p3, 0.f);
            P4[(rowbase + jj) * 64 + 2 * l + 0] = make_float4(p0, p0, p1, p1);
            P4[(rowbase + jj) * 64 + 2 * l + 1] = make_float4(p2, p2, p3, p3);
        }
    }
    __syncthreads();   // chunk 0 staged + P2 + raw visible

    // ---- phase 3: G1 = relu(P @ Wg1 + bg1) fused with Wg2 reduce --------
    // Wg1 double-buffer staged through smem, 8 chunks of 16 h-rows each.
    // warp w -> rows 4w..4w+3, all 3 regimes; lane l -> m-cols 2l, 2l+1.
    // P read pre-duplicated from smem (no pk2 movs in the hot loop).
    {
        ull acc3[3][4];
        #pragma unroll
        for (int rr = 0; rr < 3; rr++) {
            ull bgv = *(const ull*)(bg1 + rr * 64 + 2 * l);
            #pragma unroll
            for (int q = 0; q < 4; q++) acc3[rr][q] = bgv;
        }
        // P2 as ulonglong2: row stride 64 ull2 (= 64 float4)
        const ulonglong2* Pu2 = (const ulonglong2*)P2 + (4 * w) * 64;
        for (int c = 0; c < 8; c++) {
            // prefetch chunk c+1 into the other buffer
            if (c < 7) {
                const float4* srcW = (const float4*)(Wg1 + (c + 1) * 1024);
                float4* dstW = (float4*)((c & 1) ? sWg0 : sWg1);
                #pragma unroll
                for (int i = 0; i < 3; i++) {
                    int idx = i * 256 + t;
                    int rr = idx >> 8, within = idx & 255;
                    dstW[rr * 256 + within] = srcW[rr * 2048 + within];
                }
            }
            const float* bufc = (c & 1) ? sWg1 : sWg0;
            #pragma unroll
            for (int h4 = 0; h4 < 4; h4++) {
                ulonglong2 pa[4][2];   // 4 rows x 4 dup-pairs (h = 4(c*4+h4)..+3)
                #pragma unroll
                for (int q = 0; q < 4; q++) {
                    pa[q][0] = Pu2[q * 64 + 2 * (c * 4 + h4)];
                    pa[q][1] = Pu2[q * 64 + 2 * (c * 4 + h4) + 1];
                }
                #pragma unroll
                for (int rr = 0; rr < 3; rr++) {
                    const ull* Wsm = (const ull*)(bufc + rr * 1024 + h4 * 256) + l;
                    ull w0 = Wsm[0];
                    ull w1 = Wsm[32];
                    ull w2 = Wsm[64];
                    ull w3 = Wsm[96];
                    #pragma unroll
                    for (int q = 0; q < 4; q++) {
                        fma2(acc3[rr][q], pa[q][0].x, w0);
                        fma2(acc3[rr][q], pa[q][0].y, w1);
                        fma2(acc3[rr][q], pa[q][1].x, w2);
                        fma2(acc3[rr][q], pa[q][1].y, w3);
                    }
                }
            }
            __syncthreads();   // chunk c consumed; chunk c+1 staged
        }
        #pragma unroll
        for (int rr = 0; rr < 3; rr++) {
            float2 wq = *(const float2*)(Wg2 + rr * 64 + 2 * l);
            float bgr = bg2[rr];
            float reg = g_regime[rr];
            #pragma unroll
            for (int q = 0; q < 4; q++) {
                float v0, v1;
                upk2(acc3[rr][q], v0, v1);
                float s = fmaxf(v0, 0.f) * wq.x + fmaxf(v1, 0.f) * wq.y;
                #pragma unroll
                for (int off = 16; off; off >>= 1)
                    s += __shfl_xor_sync(0xffffffffu, s, off);
                if (l == 0) {
                    float gate = 1.f / (1.f + expf(-(s + bgr)));
                    gpart[rr * 32 + 4 * w + q] = gate * reg;
                }
            }
        }
    }
    __syncthreads();

    if (t < 32) {
        float gc = gpart[t] + gpart[32 + t] + gpart[64 + t];
        sc[t] = raw[t] * gc * g_amp;
    }
    __syncthreads();

    // ---- phase 5: dedupe (last wins), softmax, rank, top-k fill ---------
    if (t < 32) {
        int j = t;
        int tgj = tg[j];
        bool valid = true;
        for (int j2 = j + 1; j2 < 32; j2++)
            if (tg[j2] == tgj) valid = false;
        float sval = sc[j];
        float m = valid ? sval : -INFINITY;
        #pragma unroll
        for (int off = 16; off; off >>= 1)
            m = fmaxf(m, __shfl_xor_sync(0xffffffffu, m, off));
        float e = valid ? expf((sval - m) / TEMP) : 0.f;
        float sum = e;
        #pragma unroll
        for (int off = 16; off; off >>= 1)
            sum += __shfl_xor_sync(0xffffffffu, sum, off);
        float p = e / sum;

        unsigned vb = __ballot_sync(0xffffffffu, valid);
        int cnt = __popc(vb);
        int rank = 0;
        for (int j2 = 0; j2 < 32; j2++) {
            float p2 = __shfl_sync(0xffffffffu, p, j2);
            int  t2 = __shfl_sync(0xffffffffu, tgj, j2);
            bool v2 = (vb >> j2) & 1u;
            if (valid && v2 && j2 != j &&
                (p2 > p || (p2 == p && t2 < tgj))) rank++;
        }
        float* wout = out + (size_t)r * K_TOP;
        float* iout = out + (size_t)N_NODES * K_TOP + (size_t)r * K_TOP;
        if (valid) {
            wout[rank] = (p > THRESH) ? p : 0.f;
            if (write_idx) iout[rank] = (float)tgj;
        }
        if (j == 0 && cnt < 32) {
            int slot = cnt, v = 0;
            while (slot < 32) {
                bool member = false;
                for (int j2 = 0; j2 < 32; j2++)
                    if (((vb >> j2) & 1u) && tg[j2] == v) member = true;
                if (!member) {
                    wout[slot] = 0.f;
                    if (write_idx) iout[slot] = (float)v;
                    slot++;
                }
                v++;
            }
        }
    }
}

// ---------------------------------------------------------------------------
extern "C" void kernel_launch(void* const* d_in, const int* in_sizes, int n_in,
                              void* d_out, int out_size) {
    const float* x    = (const float*)d_in[0];
    const void*  eidx = d_in[1];
    const float* ea   = (const float*)d_in[2];
    const float* Ws1  = (const float*)d_in[3];
    const float* bs1  = (const float*)d_in[4];
    const float* ln_g = (const float*)d_in[5];
    const float* ln_b = (const float*)d_in[6];
    const float* Ws2  = (const float*)d_in[7];
    const float* bs2  = (const float*)d_in[8];
    const float* Wp   = (const float*)d_in[9];
    const float* bp   = (const float*)d_in[10];
    const float* Wr1  = (const float*)d_in[11];
    const float* br1  = (const float*)d_in[12];
    const float* Wr2  = (const float*)d_in[13];
    const float* br2  = (const float*)d_in[14];
    const float* Wg1  = (const float*)d_in[15];
    const float* bg1  = (const float*)d_in[16];
    const float* Wg2  = (const float*)d_in[17];
    const float* bg2  = (const float*)d_in[18];
    const float* Wc1  = (const float*)d_in[19];
    const float* bc1  = (const float*)d_in[20];
    const float* Wc2  = (const float*)d_in[21];
    const float* bc2  = (const float*)d_in[22];
    float* out = (float*)d_out;

    int write_idx = (out_size >= 2 * N_NODES * K_TOP) ? 1 : 0;

    cudaFuncSetAttribute(kB, cudaFuncAttributeMaxDynamicSharedMemorySize, SMEM_B_BYTES);

    kA1<<<A1_BLOCKS, 256>>>(x, Wc1, bc1, Wc2, bc2);
    kA2<<<1, 128>>>(Wr1, br1, Wr2, br2);
    kB<<<N_NODES, 256, SMEM_B_BYTES>>>(x, eidx, ea,
        Ws1, bs1, ln_g, ln_b, Ws2, bs2, Wp, bp,
        Wg1, bg1, Wg2, bg2, out, write_idx);
}

// round 17
// speedup vs baseline: 1.2372x; 1.2372x over previous
#include <cuda_runtime.h>
#include <math.h>

#define N_NODES 8192
#define F_DIM   64
#define H_DIM   128
#define R_DIM   3
#define DEG     32
#define K_TOP   32
#define E_EDGES (N_NODES*DEG)
#define TEMP    0.3f
#define NEG     0.2f
#define EPS_LN  1e-5f
#define THRESH  1e-6f

#define A1_BLOCKS 256   // 32 nodes per block

typedef unsigned long long ull;

// deterministic scratch (no atomics)
__device__ float g_part_gs[A1_BLOCKS * F_DIM];
__device__ float g_part_cont[A1_BLOCKS];
__device__ float g_regime[R_DIM];
__device__ float g_amp;

// ---------------------------------------------------------------------------
// f32x2 helpers
__device__ __forceinline__ ull pk2(float x, float y) {
    ull r;
    asm("mov.b64 %0, {%1, %2};" : "=l"(r) : "f"(x), "f"(y));
    return r;
}
__device__ __forceinline__ void upk2(ull v, float& x, float& y) {
    asm("mov.b64 {%0, %1}, %2;" : "=f"(x), "=f"(y) : "l"(v));
}
__device__ __forceinline__ void fma2(ull& d, ull a, ull b) {
    asm("fma.rn.f32x2 %0, %1, %2, %0;" : "+l"(d) : "l"(a), "l"(b));
}
// 16B read-only weight load -> two packed f32x2 operands (coalesced 512B/warp)
__device__ __forceinline__ void ldg2x2(const float* p, ull& a, ull& b) {
    asm("ld.global.nc.v2.b64 {%0, %1}, [%2];" : "=l"(a), "=l"(b) : "l"(p));
}

// ---------------------------------------------------------------------------
// A1: per-block (32 nodes) partial column sums of x, and partial contagion sums
__global__ void kA1(const float* __restrict__ x,
                    const float* __restrict__ Wc1, const float* __restrict__ bc1,
                    const float* __restrict__ Wc2, const float* __restrict__ bc2) {
    __shared__ float xs[32][64];
    __shared__ float colsum[4][64];
    __shared__ float cwarp[8];
    int t = threadIdx.x, b = blockIdx.x;
    int base = b * 32;
    for (int idx = t; idx < 32 * 64; idx += 256)
        xs[idx >> 6][idx & 63] = x[base * 64 + idx];
    __syncthreads();
    {
        int col = t & 63, g = t >> 6;
        float s = 0.f;
        #pragma unroll
        for (int rr = 0; rr < 8; rr++) s += xs[g * 8 + rr][col];
        colsum[g][col] = s;
    }
    int w = t >> 5, l = t & 31;
    float a[4][4];
    #pragma unroll
    for (int q = 0; q < 4; q++) {
        a[q][0] = bc1[l]; a[q][1] = bc1[l + 32];
        a[q][2] = bc1[l + 64]; a[q][3] = bc1[l + 96];
    }
    #pragma unroll 4
    for (int d = 0; d < 64; d++) {
        const float* Wd = Wc1 + d * 128;
        float w0 = Wd[l], w1 = Wd[l + 32], w2 = Wd[l + 64], w3 = Wd[l + 96];
        #pragma unroll
        for (int q = 0; q < 4; q++) {
            float xv = xs[w * 4 + q][d];
            a[q][0] += xv * w0; a[q][1] += xv * w1;
            a[q][2] += xv * w2; a[q][3] += xv * w3;
        }
    }
    float csum = 0.f;
    #pragma unroll
    for (int q = 0; q < 4; q++) {
        float s = fmaxf(a[q][0], 0.f) * Wc2[l]      + fmaxf(a[q][1], 0.f) * Wc2[l + 32]
                + fmaxf(a[q][2], 0.f) * Wc2[l + 64] + fmaxf(a[q][3], 0.f) * Wc2[l + 96];
        #pragma unroll
        for (int off = 16; off; off >>= 1) s += __shfl_xor_sync(0xffffffffu, s, off);
        if (l == 0) csum += 1.f / (1.f + expf(-(s + bc2[0])));
    }
    if (l == 0) cwarp[w] = csum;
    __syncthreads();
    if (t < 64) g_part_gs[b * 64 + t] = colsum[0][t] + colsum[1][t] + colsum[2][t] + colsum[3][t];
    if (t == 0) {
        float s = 0.f;
        for (int i = 0; i < 8; i++) s += cwarp[i];
        g_part_cont[b] = s;
    }
}

// ---------------------------------------------------------------------------
// A2: finalize gs mean, regime probs, contagion amp
__global__ void kA2(const float* __restrict__ Wr1, const float* __restrict__ br1,
                    const float* __restrict__ Wr2, const float* __restrict__ br2) {
    __shared__ float gs[64];
    __shared__ float hr[128];
    int t = threadIdx.x;
    if (t < 64) {
        float s = 0.f;
        for (int b = 0; b < A1_BLOCKS; b++) s += g_part_gs[b * 64 + t];
        gs[t] = s / (float)N_NODES;
    }
    __syncthreads();
    {
        float a = br1[t];
        for (int d = 0; d < 64; d++) a += gs[d] * Wr1[d * 128 + t];
        hr[t] = fmaxf(a, 0.f);
    }
    __syncthreads();
    if (t == 0) {
        float lg[3];
        for (int r = 0; r < 3; r++) {
            float a = br2[r];
            for (int h = 0; h < 128; h++) a += hr[h] * Wr2[h * 3 + r];
            lg[r] = a;
        }
        float m = fmaxf(lg[0], fmaxf(lg[1], lg[2]));
        float e0 = expf(lg[0] - m), e1 = expf(lg[1] - m), e2 = expf(lg[2] - m);
        float s = e0 + e1 + e2;
        g_regime[0] = e0 / s; g_regime[1] = e1 / s; g_regime[2] = e2 / s;
        float c = 0.f;
        for (int b = 0; b < A1_BLOCKS; b++) c += g_part_cont[b];
        g_amp = 1.f + 0.5f * (c / (float)N_NODES);
    }
}

// ---------------------------------------------------------------------------
// Main per-row kernel. Shared layout (float offsets):
//   [0:64)        sx          [64:96)   tg (int)     [96:192)  sea
//   [192:448)     base_f      [448:480) raw          [480:512) sc
//   [512:608)     gpart[3][32]
//   [608:4704)    A2 : 32 rows x 32 float4 {a,a,a',a'} (16 KB)
//                 sWg0 (12 KB Wg1 stage, buffer 0) aliases it after phase 1
//   [4704:7776)   sWg1 (12 KB Wg1 stage, buffer 1)
//   [7776:11872)  P2 : 32 rows x 128 floats plain (16 KB)
#define SM_A2    608
#define SM_WG1B  4704
#define SM_P2    7776
#define SM_TOTAL 11872
#define SMEM_B_BYTES (SM_TOTAL * 4)

__global__ void __launch_bounds__(256, 3) kB(
    const float* __restrict__ x, const void* __restrict__ eidx, const float* __restrict__ ea,
    const float* __restrict__ Ws1, const float* __restrict__ bs1,
    const float* __restrict__ ln_g, const float* __restrict__ ln_b,
    const float* __restrict__ Ws2, const float* __restrict__ bs2,
    const float* __restrict__ Wp,  const float* __restrict__ bp,
    const float* __restrict__ Wg1, const float* __restrict__ bg1,
    const float* __restrict__ Wg2, const float* __restrict__ bg2,
    float* __restrict__ out, int write_idx) {

    extern __shared__ float smf[];
    float* sx     = smf;
    int*   tg     = (int*)(smf + 64);
    float* sea    = smf + 96;
    float* base_f = smf + 192;
    float* raw    = smf + 448;
    float* sc     = smf + 480;
    float* gpart  = smf + 512;
    float* A2     = smf + SM_A2;     // dup-pair float4, 2 d per float4
    float* sWg0   = smf + SM_A2;     // aliases A2 after phase-1 mainloop
    float* sWg1   = smf + SM_WG1B;
    float* P2     = smf + SM_P2;     // plain [32][128]

    int t = threadIdx.x;
    int r = blockIdx.x;
    int w = t >> 5, l = t & 31;

    // ---- phase 0a: small loads -----------------------------------------
    if (t < 16) ((float4*)sx)[t] = ((const float4*)(x + r * 64))[t];
    if (t >= 64 && t < 96) {
        int j = t - 64;
        int e = r * DEG + j;
        const long long* p64 = (const long long*)eidx;
        int tgv;
        if (p64[32] == 1LL) tgv = (int)p64[E_EDGES + e];
        else                tgv = ((const int*)eidx)[E_EDGES + e];
        tg[j] = tgv;
    }
    if (t >= 96 && t < 192) sea[t - 96] = ea[r * 96 + (t - 96)];
    __syncthreads();

    // ---- phase 0b: gather A2 (all threads) + base_f (all threads) -------
    {
        const float4* x4 = (const float4*)x;
        float4* A4w = (float4*)A2;
        #pragma unroll
        for (int u = 0; u < 2; u++) {
            int idx = t + u * 256;                 // 512 float4 total
            int row = idx >> 4, d4 = idx & 15;
            float4 v = x4[tg[row] * 16 + d4];
            A4w[row * 32 + d4 * 2 + 0] = make_float4(v.x, v.x, v.y, v.y);
            A4w[row * 32 + d4 * 2 + 1] = make_float4(v.z, v.z, v.w, v.w);
        }
    }
    {
        // fused column c = t (0..127 -> Ws1, 128..255 -> Wp)
        const float* Wcol = (t < 128) ? (Ws1 + t) : (Wp + (t - 128));
        float acc0 = (t < 128) ? bs1[t] : bp[t - 128];
        #pragma unroll 8
        for (int d = 0; d < 64; d++)
            acc0 += sx[d] * Wcol[d * 128];
        base_f[t] = acc0;
    }
    __syncthreads();

    // ---- phase 1: fused [32 x 256] GEMM (H | P) -------------------------
    // warp w: matsel = w>>2 (0=H via Ws1, 1=P via Wp), rq = w&3 -> rows rq*8..rq*8+7
    // lane l: cols 4l..4l+3 of the 128-col mat (2 col-pairs)
    int matsel = w >> 2, rq = w & 3;
    int rowbase = rq * 8;
    const float* Wmat = matsel ? Wp : Ws1;
    const float* Wtgt = Wmat + 64 * 128 + 4 * l;
    ull acc[8][2];
    {
        const ull* bf = (const ull*)base_f + matsel * 64 + 2 * l;
        #pragma unroll
        for (int jj = 0; jj < 8; jj++) { acc[jj][0] = bf[0]; acc[jj][1] = bf[1]; }
    }
    {
        const ulonglong2* Arow = (const ulonglong2*)A2 + rowbase * 32;
        #pragma unroll 4
        for (int d2 = 0; d2 < 32; d2++) {
            ull w00, w01, w10, w11;
            ldg2x2(Wtgt + (2 * d2) * 128, w00, w01);        // d=2d2, cp0|cp1
            ldg2x2(Wtgt + (2 * d2 + 1) * 128, w10, w11);    // d=2d2+1
            #pragma unroll
            for (int jj = 0; jj < 8; jj++) {
                ulonglong2 av = Arow[jj * 32 + d2];
                fma2(acc[jj][0], av.x, w00); fma2(acc[jj][1], av.x, w01);
                fma2(acc[jj][0], av.y, w10); fma2(acc[jj][1], av.y, w11);
            }
        }
        // edge-attr tail (rows 128..130 of the fused weight)
        #pragma unroll
        for (int k = 0; k < 3; k++) {
            ull e0, e1;
            ldg2x2(Wmat + (128 + k) * 128 + 4 * l, e0, e1);
            #pragma unroll
            for (int jj = 0; jj < 8; jj++) {
                float sv = sea[(rowbase + jj) * 3 + k];
                ull sp = pk2(sv, sv);
                fma2(acc[jj][0], sp, e0); fma2(acc[jj][1], sp, e1);
            }
        }
    }
    __syncthreads();   // A2 reads done everywhere; sWg0 may now alias it

    // ---- stage Wg1 chunk 0 into sWg0 (LDGs in flight during epilogue) ---
    {
        const float4* srcW = (const float4*)(Wg1);
        float4* dstW = (float4*)sWg0;
        #pragma unroll
        for (int i = 0; i < 3; i++) {
            int idx = i * 256 + t;
            int rr = idx >> 8, within = idx & 255;
            dstW[rr * 256 + within] = srcW[rr * 2048 + within];
        }
    }

    // ---- phase 1 epilogue ----------------------------------------------
    if (matsel == 0) {
        // H-warps: full row in-warp -> fused LayerNorm + LeakyReLU + score
        float4 lgv = *(const float4*)(ln_g + 4 * l);
        float4 lbv = *(const float4*)(ln_b + 4 * l);
        float4 wsv = *(const float4*)(Ws2 + 4 * l);
        float bias2 = bs2[0];
        #pragma unroll
        for (int jj = 0; jj < 8; jj++) {
            float v0, v1, v2, v3;
            upk2(acc[jj][0], v0, v1); upk2(acc[jj][1], v2, v3);
            float s  = v0 + v1 + v2 + v3;
            float ss = v0 * v0 + v1 * v1 + v2 * v2 + v3 * v3;
            #pragma unroll
            for (int off = 16; off; off >>= 1) {
                s  += __shfl_xor_sync(0xffffffffu, s, off);
                ss += __shfl_xor_sync(0xffffffffu, ss, off);
            }
            float mu  = s * (1.f / 128.f);
            float var = fmaxf(ss * (1.f / 128.f) - mu * mu, 0.f);
            float inv = rsqrtf(var + EPS_LN);
            float h0 = (v0 - mu) * inv * lgv.x + lbv.x;
            float h1 = (v1 - mu) * inv * lgv.y + lbv.y;
            float h2 = (v2 - mu) * inv * lgv.z + lbv.z;
            float h3 = (v3 - mu) * inv * lgv.w + lbv.w;
            h0 = h0 >= 0.f ? h0 : NEG * h0;
            h1 = h1 >= 0.f ? h1 : NEG * h1;
            h2 = h2 >= 0.f ? h2 : NEG * h2;
            h3 = h3 >= 0.f ? h3 : NEG * h3;
            float contrib = h0 * wsv.x + h1 * wsv.y + h2 * wsv.z + h3 * wsv.w;
            #pragma unroll
            for (int off = 16; off; off >>= 1)
                contrib += __shfl_xor_sync(0xffffffffu, contrib, off);
            if (l == 0) raw[rowbase + jj] = contrib + bias2;
        }
    } else {
        // P-warps: relu + plain float4 store
        #pragma unroll
        for (int jj = 0; jj < 8; jj++) {
            float p0, p1, p2, p3;
            upk2(acc[jj][0], p0, p1); upk2(acc[jj][1], p2, p3);
            p0 = fmaxf(p0, 0.f); p1 = fmaxf(p1, 0.f);
            p2 = fmaxf(p2, 0.f); p3 = fmaxf(p3, 0.f);
            *(float4*)(P2 + (rowbase + jj) * 128 + 4 * l) = make_float4(p0, p1, p2, p3);
        }
    }
    __syncthreads();   // chunk 0 staged + P2 + raw visible

    // ---- phase 3: G1 = relu(P @ Wg1 + bg1) fused with Wg2 reduce --------
    // Wg1 double-buffer staged through smem, 8 chunks of 16 h-rows each.
    // warp w -> rows 4w..4w+3, all 3 regimes; lane l -> m-cols 2l, 2l+1.
    {
        ull acc3[3][4];
        #pragma unroll
        for (int rr = 0; rr < 3; rr++) {
            ull bgv = *(const ull*)(bg1 + rr * 64 + 2 * l);
            #pragma unroll
            for (int q = 0; q < 4; q++) acc3[rr][q] = bgv;
        }
        const float* Prow = P2 + (4 * w) * 128;
        for (int c = 0; c < 8; c++) {
            // prefetch chunk c+1 into the other buffer
            if (c < 7) {
                const float4* srcW = (const float4*)(Wg1 + (c + 1) * 1024);
                float4* dstW = (float4*)((c & 1) ? sWg0 : sWg1);
                #pragma unroll
                for (int i = 0; i < 3; i++) {
                    int idx = i * 256 + t;
                    int rr = idx >> 8, within = idx & 255;
                    dstW[rr * 256 + within] = srcW[rr * 2048 + within];
                }
            }
            const float* bufc = (c & 1) ? sWg1 : sWg0;
            #pragma unroll
            for (int h4 = 0; h4 < 4; h4++) {
                int hg = c * 4 + h4;   // global float4 index into P row
                ull pp[4][4];
                #pragma unroll
                for (int q = 0; q < 4; q++) {
                    float4 pv = ((const float4*)(Prow + q * 128))[hg];
                    pp[q][0] = pk2(pv.x, pv.x); pp[q][1] = pk2(pv.y, pv.y);
                    pp[q][2] = pk2(pv.z, pv.z); pp[q][3] = pk2(pv.w, pv.w);
                }
                #pragma unroll
                for (int rr = 0; rr < 3; rr++) {
                    const ull* Wsm = (const ull*)(bufc + rr * 1024 + h4 * 256) + l;
                    ull w0 = Wsm[0];
                    ull w1 = Wsm[32];
                    ull w2 = Wsm[64];
                    ull w3 = Wsm[96];
                    #pragma unroll
                    for (int q = 0; q < 4; q++) {
                        fma2(acc3[rr][q], pp[q][0], w0);
                        fma2(acc3[rr][q], pp[q][1], w1);
                        fma2(acc3[rr][q], pp[q][2], w2);
                        fma2(acc3[rr][q], pp[q][3], w3);
                    }
                }
            }
            __syncthreads();   // chunk c consumed; chunk c+1 staged
        }
        #pragma unroll
        for (int rr = 0; rr < 3; rr++) {
            float2 wq = *(const float2*)(Wg2 + rr * 64 + 2 * l);
            float bgr = bg2[rr];
            float reg = g_regime[rr];
            #pragma unroll
            for (int q = 0; q < 4; q++) {
                float v0, v1;
                upk2(acc3[rr][q], v0, v1);
                float s = fmaxf(v0, 0.f) * wq.x + fmaxf(v1, 0.f) * wq.y;
                #pragma unroll
                for (int off = 16; off; off >>= 1)
                    s += __shfl_xor_sync(0xffffffffu, s, off);
                if (l == 0) {
                    float gate = 1.f / (1.f + expf(-(s + bgr)));
                    gpart[rr * 32 + 4 * w + q] = gate * reg;
                }
            }
        }
    }
    __syncthreads();

    if (t < 32) {
        float gc = gpart[t] + gpart[32 + t] + gpart[64 + t];
        sc[t] = raw[t] * gc * g_amp;
    }
    __syncthreads();

    // ---- phase 5: dedupe (last wins), softmax, rank, top-k fill ---------
    if (t < 32) {
        int j = t;
        int tgj = tg[j];
        bool valid = true;
        for (int j2 = j + 1; j2 < 32; j2++)
            if (tg[j2] == tgj) valid = false;
        float sval = sc[j];
        float m = valid ? sval : -INFINITY;
        #pragma unroll
        for (int off = 16; off; off >>= 1)
            m = fmaxf(m, __shfl_xor_sync(0xffffffffu, m, off));
        float e = valid ? expf((sval - m) / TEMP) : 0.f;
        float sum = e;
        #pragma unroll
        for (int off = 16; off; off >>= 1)
            sum += __shfl_xor_sync(0xffffffffu, sum, off);
        float p = e / sum;

        unsigned vb = __ballot_sync(0xffffffffu, valid);
        int cnt = __popc(vb);
        int rank = 0;
        for (int j2 = 0; j2 < 32; j2++) {
            float p2 = __shfl_sync(0xffffffffu, p, j2);
            int  t2 = __shfl_sync(0xffffffffu, tgj, j2);
            bool v2 = (vb >> j2) & 1u;
            if (valid && v2 && j2 != j &&
                (p2 > p || (p2 == p && t2 < tgj))) rank++;
        }
        float* wout = out + (size_t)r * K_TOP;
        float* iout = out + (size_t)N_NODES * K_TOP + (size_t)r * K_TOP;
        if (valid) {
            wout[rank] = (p > THRESH) ? p : 0.f;
            if (write_idx) iout[rank] = (float)tgj;
        }
        if (j == 0 && cnt < 32) {
            int slot = cnt, v = 0;
            while (slot < 32) {
                bool member = false;
                for (int j2 = 0; j2 < 32; j2++)
                    if (((vb >> j2) & 1u) && tg[j2] == v) member = true;
                if (!member) {
                    wout[slot] = 0.f;
                    if (write_idx) iout[slot] = (float)v;
                    slot++;
                }
                v++;
            }
        }
    }
}

// ---------------------------------------------------------------------------
extern "C" void kernel_launch(void* const* d_in, const int* in_sizes, int n_in,
                              void* d_out, int out_size) {
    const float* x    = (const float*)d_in[0];
    const void*  eidx = d_in[1];
    const float* ea   = (const float*)d_in[2];
    const float* Ws1  = (const float*)d_in[3];
    const float* bs1  = (const float*)d_in[4];
    const float* ln_g = (const float*)d_in[5];
    const float* ln_b = (const float*)d_in[6];
    const float* Ws2  = (const float*)d_in[7];
    const float* bs2  = (const float*)d_in[8];
    const float* Wp   = (const float*)d_in[9];
    const float* bp   = (const float*)d_in[10];
    const float* Wr1  = (const float*)d_in[11];
    const float* br1  = (const float*)d_in[12];
    const float* Wr2  = (const float*)d_in[13];
    const float* br2  = (const float*)d_in[14];
    const float* Wg1  = (const float*)d_in[15];
    const float* bg1  = (const float*)d_in[16];
    const float* Wg2  = (const float*)d_in[17];
    const float* bg2  = (const float*)d_in[18];
    const float* Wc1  = (const float*)d_in[19];
    const float* bc1  = (const float*)d_in[20];
    const float* Wc2  = (const float*)d_in[21];
    const float* bc2  = (const float*)d_in[22];
    float* out = (float*)d_out;

    int write_idx = (out_size >= 2 * N_NODES * K_TOP) ? 1 : 0;

    cudaFuncSetAttribute(kB, cudaFuncAttributeMaxDynamicSharedMemorySize, SMEM_B_BYTES);

    kA1<<<A1_BLOCKS, 256>>>(x, Wc1, bc1, Wc2, bc2);
    kA2<<<1, 128>>>(Wr1, br1, Wr2, br2);
    kB<<<N_NODES, 256, SMEM_B_BYTES>>>(x, eidx, ea,
        Ws1, bs1, ln_g, ln_b, Ws2, bs2, Wp, bp,
        Wg1, bg1, Wg2, bg2, out, write_idx);
}